// round 1
// baseline (speedup 1.0000x reference)
#include <cuda_runtime.h>
#include <cstdint>

#define B_       8
#define C_       96
#define H_       128
#define W_       416
#define ND_      49

#define CH       12            // channels per stage
#define NSTAGE   8             // 96 / 12
#define YPAD     56            // zero pad (covers d up to 55 incl. masked tail)
#define YROW     472           // YPAD + 416
#define XFLOATS  (CH * W_)     // 4992
#define YFLOATS  (CH * YROW)   // 5664
#define BUFFLOATS (XFLOATS + YFLOATS)  // 10656
#define SMEM_BYTES (2 * BUFFLOATS * 4) // 85248

#define THREADS  384
#define NWG      52            // w-groups of 8  (52*8 = 416 exact)
#define NDG      7             // d-groups of 8  (covers 0..55, mask >=49)

__device__ __forceinline__ void cp_async16(uint32_t saddr, const void* g) {
    asm volatile("cp.async.cg.shared.global [%0], [%1], 16;" :: "r"(saddr), "l"(g));
}

__device__ __forceinline__ void fill_stage(const float* __restrict__ xbh,
                                           const float* __restrict__ ybh,
                                           int c0, float* buf, int tid) {
    // per stage: CH rows of 104 float4 for x, same for y
    const int NF4 = CH * (W_ / 4);  // 1248
    uint32_t xs = (uint32_t)__cvta_generic_to_shared(buf);
    uint32_t ys = (uint32_t)__cvta_generic_to_shared(buf + XFLOATS);
    for (int i = tid; i < 2 * NF4; i += THREADS) {
        if (i < NF4) {
            int r = i / (W_ / 4);
            int col = (i - r * (W_ / 4)) * 4;
            cp_async16(xs + (uint32_t)(r * W_ + col) * 4u,
                       xbh + (size_t)(c0 + r) * (H_ * W_) + col);
        } else {
            int j = i - NF4;
            int r = j / (W_ / 4);
            int col = (j - r * (W_ / 4)) * 4;
            cp_async16(ys + (uint32_t)(r * YROW + YPAD + col) * 4u,
                       ybh + (size_t)(c0 + r) * (H_ * W_) + col);
        }
    }
}

extern __shared__ float smem[];

__global__ void __launch_bounds__(THREADS, 1)
costvol_kernel(const float* __restrict__ x, const float* __restrict__ y,
               float* __restrict__ out) {
    const int h   = blockIdx.x;
    const int b   = blockIdx.y;
    const int tid = threadIdx.x;

    const float* xbh = x + ((size_t)b * C_ * H_ + h) * W_;  // x[b][0][h][:]
    const float* ybh = y + ((size_t)b * C_ * H_ + h) * W_;

    // zero the left pads of both y buffers (written once; data region never touches it)
    for (int i = tid; i < 2 * CH * YPAD; i += THREADS) {
        int bufi = i / (CH * YPAD);
        int rem  = i - bufi * (CH * YPAD);
        int r    = rem / YPAD;
        int cc   = rem - r * YPAD;
        smem[bufi * BUFFLOATS + XFLOATS + r * YROW + cc] = 0.0f;
    }

    const int wg = tid % NWG;
    const int dg = tid / NWG;           // 0..7 (dg==7 are the 20 filler threads)
    const bool active = (dg < NDG);
    const int wbase = wg * 8;
    const int dbase = dg * 8;

    float acc[8][8];
#pragma unroll
    for (int i = 0; i < 8; ++i)
#pragma unroll
        for (int j = 0; j < 8; ++j) acc[i][j] = 0.0f;

    fill_stage(xbh, ybh, 0, smem, tid);
    asm volatile("cp.async.commit_group;");

    for (int s = 0; s < NSTAGE; ++s) {
        if (s + 1 < NSTAGE) {
            fill_stage(xbh, ybh, (s + 1) * CH, smem + ((s + 1) & 1) * BUFFLOATS, tid);
            asm volatile("cp.async.commit_group;");
            asm volatile("cp.async.wait_group 1;");
        } else {
            asm volatile("cp.async.wait_group 0;");
        }
        __syncthreads();

        if (active) {
            const float* xs = smem + (s & 1) * BUFFLOATS + wbase;
            // window base: logical offset YPAD + wbase - dbase - 8  (== 0 mod 4)
            const float* ys = smem + (s & 1) * BUFFLOATS + XFLOATS
                              + (YPAD + wbase - dbase - 8);
#pragma unroll 2
            for (int c = 0; c < CH; ++c) {
                float4 xq0 = *(const float4*)(xs + c * W_);
                float4 xq1 = *(const float4*)(xs + c * W_ + 4);
                float xv[8] = {xq0.x, xq0.y, xq0.z, xq0.w,
                               xq1.x, xq1.y, xq1.z, xq1.w};
                float yv[16];
#pragma unroll
                for (int q = 0; q < 4; ++q) {
                    float4 t = *(const float4*)(ys + c * YROW + q * 4);
                    yv[q * 4 + 0] = t.x; yv[q * 4 + 1] = t.y;
                    yv[q * 4 + 2] = t.z; yv[q * 4 + 3] = t.w;
                }
#pragma unroll
                for (int dd = 0; dd < 8; ++dd)
#pragma unroll
                    for (int ww = 0; ww < 8; ++ww)
                        acc[dd][ww] = fmaf(xv[ww], yv[ww - dd + 8], acc[dd][ww]);
            }
        }
        __syncthreads();
    }

    if (active) {
        float* obh = out + (size_t)b * ND_ * H_ * W_ + (size_t)h * W_ + wbase;
#pragma unroll
        for (int dd = 0; dd < 8; ++dd) {
            int d = dbase + dd;
            if (d < ND_) {
                float4* p = (float4*)(obh + (size_t)d * (H_ * W_));
                p[0] = make_float4(acc[dd][0], acc[dd][1], acc[dd][2], acc[dd][3]);
                p[1] = make_float4(acc[dd][4], acc[dd][5], acc[dd][6], acc[dd][7]);
            }
        }
    }
}

extern "C" void kernel_launch(void* const* d_in, const int* in_sizes, int n_in,
                              void* d_out, int out_size) {
    const float* x = (const float*)d_in[0];
    const float* y = (const float*)d_in[1];
    float* out = (float*)d_out;

    cudaFuncSetAttribute(costvol_kernel,
                         cudaFuncAttributeMaxDynamicSharedMemorySize, SMEM_BYTES);

    dim3 grid(H_, B_);
    costvol_kernel<<<grid, THREADS, SMEM_BYTES>>>(x, y, out);
}

// round 5
// speedup vs baseline: 1.1811x; 1.1811x over previous
#include <cuda_runtime.h>
#include <cstdint>

#define B_       8
#define C_       96
#define H_       128
#define W_       416
#define ND_      49

#define CH       12            // channels per stage
#define NSTAGE   8             // 96 / 12
#define YPAD     56
#define YROW     472           // YPAD + 416
#define XFLOATS  (CH * W_)     // 4992
#define YFLOATS  (CH * YROW)   // 5664
#define BUFFLOATS (XFLOATS + YFLOATS)  // 10656
#define SMEM_BYTES (2 * BUFFLOATS * 4) // 85248

#define THREADS  384
#define NWG      52
#define NDG      7

typedef unsigned long long u64;

// XOR swizzle at 16B-block granularity: flips bit0 of the block index with
// bit3. Lane patterns g = c + 2i become conflict-free within each aligned
// 8-lane quarter.
__device__ __forceinline__ uint32_t swz_block(uint32_t g) {
    return g ^ ((g >> 3) & 1u);
}
// logical float offset (mult of 4) -> physical byte offset within buffer
__device__ __forceinline__ uint32_t swz16B(uint32_t fofs) {
    return swz_block(fofs >> 2) << 4;
}
// scalar float offset -> physical float offset
__device__ __forceinline__ uint32_t swzF(uint32_t fofs) {
    return (swz_block(fofs >> 2) << 2) | (fofs & 3u);
}

__device__ __forceinline__ void cp_async16(uint32_t saddr, const void* g) {
    asm volatile("cp.async.cg.shared.global [%0], [%1], 16;" :: "r"(saddr), "l"(g));
}

__device__ __forceinline__ u64 pack2(float a, float b) {
    u64 r;
    asm("mov.b64 %0, {%1, %2};" : "=l"(r) : "f"(a), "f"(b));
    return r;
}
__device__ __forceinline__ void fma2(u64& d, u64 a, u64 b) {
    asm("fma.rn.f32x2 %0, %1, %2, %0;" : "+l"(d) : "l"(a), "l"(b));
}
__device__ __forceinline__ void unpack2(u64 v, float& lo, float& hi) {
    asm("mov.b64 {%0, %1}, %2;" : "=f"(lo), "=f"(hi) : "l"(v));
}

extern __shared__ float smem[];

__device__ __forceinline__ void fill_stage(const float* __restrict__ xbh,
                                           const float* __restrict__ ybh,
                                           int c0, uint32_t bufbase_bytes, int tid) {
    const int NF4 = CH * (W_ / 4);  // 1248
    uint32_t sb = (uint32_t)__cvta_generic_to_shared(smem) + bufbase_bytes;
    for (int i = tid; i < 2 * NF4; i += THREADS) {
        if (i < NF4) {
            int r = i / (W_ / 4);
            int col = (i - r * (W_ / 4)) * 4;
            cp_async16(sb + swz16B((uint32_t)(r * W_ + col)),
                       xbh + (size_t)(c0 + r) * (H_ * W_) + col);
        } else {
            int j = i - NF4;
            int r = j / (W_ / 4);
            int col = (j - r * (W_ / 4)) * 4;
            cp_async16(sb + swz16B((uint32_t)(XFLOATS + r * YROW + YPAD + col)),
                       ybh + (size_t)(c0 + r) * (H_ * W_) + col);
        }
    }
}

__device__ __forceinline__ float4 lds4(const float* buf, uint32_t fofs) {
    return *(const float4*)(buf + swz16B(fofs) / 4);
}

__global__ void __launch_bounds__(THREADS, 1)
costvol_kernel(const float* __restrict__ x, const float* __restrict__ y,
               float* __restrict__ out) {
    const int h   = blockIdx.x;
    const int b   = blockIdx.y;
    const int tid = threadIdx.x;

    const float* xbh = x + ((size_t)b * C_ * H_ + h) * W_;
    const float* ybh = y + ((size_t)b * C_ * H_ + h) * W_;

    // zero the swizzled left pads of both stage buffers
    for (int i = tid; i < 2 * CH * YPAD; i += THREADS) {
        int bufi = i / (CH * YPAD);
        int rem  = i - bufi * (CH * YPAD);
        int r    = rem / YPAD;
        int cc   = rem - r * YPAD;
        smem[bufi * BUFFLOATS + swzF((uint32_t)(XFLOATS + r * YROW + cc))] = 0.0f;
    }

    const int wg = tid % NWG;
    const int dg = tid / NWG;
    const bool active = (dg < NDG);
    const int wbase = wg * 8;
    const int dbase = dg * 8;

    u64 acc[8][4];
#pragma unroll
    for (int i = 0; i < 8; ++i)
#pragma unroll
        for (int j = 0; j < 4; ++j) acc[i][j] = 0ull;

    fill_stage(xbh, ybh, 0, 0, tid);
    asm volatile("cp.async.commit_group;");

    for (int s = 0; s < NSTAGE; ++s) {
        if (s + 1 < NSTAGE) {
            fill_stage(xbh, ybh, (s + 1) * CH,
                       (uint32_t)(((s + 1) & 1) * BUFFLOATS * 4), tid);
            asm volatile("cp.async.commit_group;");
            asm volatile("cp.async.wait_group 1;");
        } else {
            asm volatile("cp.async.wait_group 0;");
        }
        __syncthreads();

        if (active) {
            const float* buf = smem + (s & 1) * BUFFLOATS;
            const uint32_t xbase = (uint32_t)wbase;
            const uint32_t ybase = (uint32_t)(XFLOATS + YPAD + wbase - dbase - 8);
#pragma unroll 2
            for (int c = 0; c < CH; ++c) {
                float4 xq0 = lds4(buf, xbase + c * W_);
                float4 xq1 = lds4(buf, xbase + c * W_ + 4);
                u64 xp[4];
                xp[0] = pack2(xq0.x, xq0.y);
                xp[1] = pack2(xq0.z, xq0.w);
                xp[2] = pack2(xq1.x, xq1.y);
                xp[3] = pack2(xq1.z, xq1.w);

                float yv[16];
#pragma unroll
                for (int q = 0; q < 4; ++q) {
                    float4 t = lds4(buf, ybase + c * YROW + q * 4);
                    yv[q * 4 + 0] = t.x; yv[q * 4 + 1] = t.y;
                    yv[q * 4 + 2] = t.z; yv[q * 4 + 3] = t.w;
                }
                u64 yp[15];  // yp[k] = (yv[k], yv[k+1]), k = 1..14
#pragma unroll
                for (int k = 1; k < 15; ++k) yp[k] = pack2(yv[k], yv[k + 1]);

#pragma unroll
                for (int dd = 0; dd < 8; ++dd)
#pragma unroll
                    for (int p = 0; p < 4; ++p)
                        fma2(acc[dd][p], xp[p], yp[8 - dd + 2 * p]);
            }
        }
        __syncthreads();
    }

    if (active) {
        float* obh = out + (size_t)b * ND_ * H_ * W_ + (size_t)h * W_ + wbase;
#pragma unroll
        for (int dd = 0; dd < 8; ++dd) {
            int d = dbase + dd;
            if (d < ND_) {
                float4* p = (float4*)(obh + (size_t)d * (H_ * W_));
                float v0, v1, v2, v3, v4, v5, v6, v7;
                unpack2(acc[dd][0], v0, v1);
                unpack2(acc[dd][1], v2, v3);
                unpack2(acc[dd][2], v4, v5);
                unpack2(acc[dd][3], v6, v7);
                p[0] = make_float4(v0, v1, v2, v3);
                p[1] = make_float4(v4, v5, v6, v7);
            }
        }
    }
}

extern "C" void kernel_launch(void* const* d_in, const int* in_sizes, int n_in,
                              void* d_out, int out_size) {
    const float* x = (const float*)d_in[0];
    const float* y = (const float*)d_in[1];
    float* out = (float*)d_out;

    cudaFuncSetAttribute(costvol_kernel,
                         cudaFuncAttributeMaxDynamicSharedMemorySize, SMEM_BYTES);

    dim3 grid(H_, B_);
    costvol_kernel<<<grid, THREADS, SMEM_BYTES>>>(x, y, out);
}

// round 17
// speedup vs baseline: 1.4897x; 1.2613x over previous
#include <cuda_runtime.h>
#include <cstdint>

#define B_       8
#define C_       96
#define H_       128
#define W_       416
#define HW_      (H_ * W_)
#define ND_      49

#define CH       12
#define NSTAGE   8
#define YPAD     56
#define WPADX    448              // x row floats (1792 B = 7*256)
#define YROW2    512              // y row floats (2048 B = 8*256)
#define XF2      (CH * WPADX)     // 5376 floats
#define YF2      (CH * YROW2)     // 6144 floats
#define BUF2     (XF2 + YF2)      // 11520 floats
#define BUFBYTES (BUF2 * 4)       // 46080 (= 180*256)
#define SMEM_BYTES (2 * BUFBYTES) // 92160

#define THREADS  384
#define NWG      52
#define NDG      7
#define NF4      (CH * (W_ / 4))  // 1248 float4 per array per stage

typedef unsigned long long u64;

// physical = logical ^ ((logical>>3)&0x10)  (bit4 ^= bit7), byte addresses.
__device__ __forceinline__ uint32_t phys(uint32_t a) {
    return a ^ ((a >> 3) & 0x10u);
}

__device__ __forceinline__ void cp_async16(uint32_t saddr, const void* g) {
    asm volatile("cp.async.cg.shared.global [%0], [%1], 16;" :: "r"(saddr), "l"(g));
}

__device__ __forceinline__ void fma2(u64& d, u64 a, u64 b) {
    asm("fma.rn.f32x2 %0, %1, %2, %0;" : "+l"(d) : "l"(a), "l"(b));
}
// (hi of a, lo of b) -> aligned u64 pair; 2 SASS MOVs
__device__ __forceinline__ u64 hilo(u64 a, u64 b) {
    u64 r;
    asm("{\n\t"
        ".reg .b32 al, ah, bl, bh;\n\t"
        "mov.b64 {al, ah}, %1;\n\t"
        "mov.b64 {bl, bh}, %2;\n\t"
        "mov.b64 %0, {ah, bl};\n\t"
        "}" : "=l"(r) : "l"(a), "l"(b));
    return r;
}
__device__ __forceinline__ void unpack2(u64 v, float& lo, float& hi) {
    asm("mov.b64 {%0, %1}, %2;" : "=f"(lo), "=f"(hi) : "l"(v));
}
__device__ __forceinline__ u64 d2u(double d) { return __double_as_longlong(d); }

extern __shared__ float smem[];

__global__ void __launch_bounds__(THREADS, 1)
costvol_kernel(const float* __restrict__ x, const float* __restrict__ y,
               float* __restrict__ out) {
    const int h   = blockIdx.x;
    const int b   = blockIdx.y;
    const int tid = threadIdx.x;

    const float* xbh = x + ((size_t)b * C_ * H_ + h) * W_;
    const float* ybh = y + ((size_t)b * C_ * H_ + h) * W_;

    char* sm = (char*)smem;
    const uint32_t sms = (uint32_t)__cvta_generic_to_shared(smem);

    // zero left pads of y rows, both buffers (one-time)
    for (int i = tid; i < 2 * CH * YPAD; i += THREADS) {
        int bufi = i / (CH * YPAD);
        int rem  = i - bufi * (CH * YPAD);
        int r    = rem / YPAD;
        int cc   = rem - r * YPAD;
        uint32_t byte = (uint32_t)(XF2 + r * YROW2 + cc) * 4u;
        *(float*)(sm + bufi * BUFBYTES + phys(byte)) = 0.0f;
    }

    // ---- precompute fill slots (j=0..2 always valid; j=3 iff tid < 96) ----
    const float* gx[4]; const float* gy[4];
    uint32_t sx[4], sy[4];
#pragma unroll
    for (int j = 0; j < 4; ++j) {
        int i = tid + j * THREADS;
        int ii = (i < NF4) ? i : 0;
        int r = ii / 104;
        int c4 = ii - r * 104;            // float4 column
        gx[j] = xbh + (size_t)r * HW_ + c4 * 4;
        gy[j] = ybh + (size_t)r * HW_ + c4 * 4;
        sx[j] = sms + phys((uint32_t)(r * WPADX + c4 * 4) * 4u);
        sy[j] = sms + phys((uint32_t)(XF2 + r * YROW2 + YPAD + c4 * 4) * 4u);
    }
    const bool j3 = (tid < NF4 - 3 * THREADS);  // tid < 96

    const int wg = tid % NWG;
    const int dg = tid / NWG;
    const bool active = (dg < NDG);
    const int wbase = wg * 8;
    const int dbase = dg * 8;

    // ---- precompute physical read bases (swizzle hoisted out of the loop) ----
    const uint32_t bx0 = phys((uint32_t)(wbase)     * 4u);
    const uint32_t bx1 = phys((uint32_t)(wbase + 4) * 4u);
    const int ylog = XF2 + YPAD + wbase - dbase - 8;
    uint32_t by[4];
#pragma unroll
    for (int q = 0; q < 4; ++q) by[q] = phys((uint32_t)(ylog + 4 * q) * 4u);

    u64 acc[8][4];
#pragma unroll
    for (int i = 0; i < 8; ++i)
#pragma unroll
        for (int j = 0; j < 4; ++j) acc[i][j] = 0ull;

    // ---- stage 0 fill ----
    {
#pragma unroll
        for (int j = 0; j < 3; ++j) {
            cp_async16(sx[j], gx[j]); cp_async16(sy[j], gy[j]);
        }
        if (j3) { cp_async16(sx[3], gx[3]); cp_async16(sy[3], gy[3]); }
#pragma unroll
        for (int j = 0; j < 4; ++j) { gx[j] += CH * HW_; gy[j] += CH * HW_; }
        asm volatile("cp.async.commit_group;");
    }

    for (int s = 0; s < NSTAGE; ++s) {
        if (s + 1 < NSTAGE) {
            uint32_t sbuf = (uint32_t)(((s + 1) & 1) * BUFBYTES);
#pragma unroll
            for (int j = 0; j < 3; ++j) {
                cp_async16(sx[j] + sbuf, gx[j]); cp_async16(sy[j] + sbuf, gy[j]);
            }
            if (j3) { cp_async16(sx[3] + sbuf, gx[3]); cp_async16(sy[3] + sbuf, gy[3]); }
#pragma unroll
            for (int j = 0; j < 4; ++j) { gx[j] += CH * HW_; gy[j] += CH * HW_; }
            asm volatile("cp.async.commit_group;");
            asm volatile("cp.async.wait_group 1;");
        } else {
            asm volatile("cp.async.wait_group 0;");
        }
        __syncthreads();

        if (active) {
            const char* base = sm + (s & 1) * BUFBYTES;
#pragma unroll
            for (int c = 0; c < CH; ++c) {
                const int xo = c * (WPADX * 4);   // 1792*c
                const int yo = c * (YROW2 * 4);   // 2048*c

                double2 xa = *(const double2*)(base + bx0 + xo);
                double2 xb = *(const double2*)(base + bx1 + xo);
                u64 xp[4] = { d2u(xa.x), d2u(xa.y), d2u(xb.x), d2u(xb.y) };

                u64 ye[8];
#pragma unroll
                for (int q = 0; q < 4; ++q) {
                    double2 t = *(const double2*)(base + by[q] + yo);
                    ye[2 * q]     = d2u(t.x);
                    ye[2 * q + 1] = d2u(t.y);
                }
                u64 yodd[7];
#pragma unroll
                for (int j = 0; j < 7; ++j) yodd[j] = hilo(ye[j], ye[j + 1]);

                // even dd: y pair index k = 8-dd+2p (even) -> ye[(8-dd)/2 + p]
#pragma unroll
                for (int dh = 0; dh < 4; ++dh)      // dd = 2*dh
#pragma unroll
                    for (int p = 0; p < 4; ++p)
                        fma2(acc[2 * dh][p], xp[p], ye[4 - dh + p]);
                // odd dd: k = 8-dd+2p (odd) -> yodd[(7-dd)/2 + p]
#pragma unroll
                for (int dh = 0; dh < 4; ++dh)      // dd = 2*dh+1
#pragma unroll
                    for (int p = 0; p < 4; ++p)
                        fma2(acc[2 * dh + 1][p], xp[p], yodd[3 - dh + p]);
            }
        }
        __syncthreads();
    }

    if (active) {
        float* obh = out + (size_t)b * ND_ * H_ * W_ + (size_t)h * W_ + wbase;
#pragma unroll
        for (int dd = 0; dd < 8; ++dd) {
            int d = dbase + dd;
            if (d < ND_) {
                float4* p = (float4*)(obh + (size_t)d * HW_);
                float v0, v1, v2, v3, v4, v5, v6, v7;
                unpack2(acc[dd][0], v0, v1);
                unpack2(acc[dd][1], v2, v3);
                unpack2(acc[dd][2], v4, v5);
                unpack2(acc[dd][3], v6, v7);
                p[0] = make_float4(v0, v1, v2, v3);
                p[1] = make_float4(v4, v5, v6, v7);
            }
        }
    }
}

extern "C" void kernel_launch(void* const* d_in, const int* in_sizes, int n_in,
                              void* d_out, int out_size) {
    const float* x = (const float*)d_in[0];
    const float* y = (const float*)d_in[1];
    float* out = (float*)d_out;

    cudaFuncSetAttribute(costvol_kernel,
                         cudaFuncAttributeMaxDynamicSharedMemorySize, SMEM_BYTES);

    dim3 grid(H_, B_);
    costvol_kernel<<<grid, THREADS, SMEM_BYTES>>>(x, y, out);
}